// round 12
// baseline (speedup 1.0000x reference)
#include <cuda_runtime.h>
#include <cuda_bf16.h>
#include <cuda_fp8.h>
#include <cstdint>
#include <math.h>

#define N2     4096
#define D      512
#define HALF_N 2048
#define NTILE  32            // 4096/128 tiles per dim
#define NBLK   528           // upper-triangular tiles: 32*33/2
#define NCTA   264           // 2 tiles per CTA; one 2-CTA/SM residency wave
#define NPART  96            // slots/row: 64 direct (tj*2+wc) + 32 transposed (ti)
#define ALPHA  1.69864360f   // sqrt(2*log2 e)
#define QS     32.0f
#define SCI    (1.0f / 1024.0f)
#define LN2S   (0.69314718056f / 1024.0f)

__device__ uint8_t g_xq[N2 * D];         // normalized, alpha*32-scaled e4m3 (2 MB)
__device__ float g_part[N2 * NPART];     // zero-init; unwritten slots stay 0
__device__ float g_pos[N2];              // positive logit per row
__device__ double g_blk[32];             // per-block loss partials
__device__ int g_rdy[NTILE];             // per-128-row-block arrival counters (8 each)
__device__ int g_cnt;                    // finalize counter (self-resetting)

__device__ __forceinline__ uint32_t smem_u32(const void* p) {
    uint32_t a;
    asm("{ .reg .u64 t; cvta.to.shared.u64 t, %1; cvt.u32.u64 %0, t; }" : "=r"(a) : "l"(p));
    return a;
}
__device__ __forceinline__ float ex2f(float x) {
    float y; asm("ex2.approx.f32 %0, %1;" : "=f"(y) : "f"(x)); return y;
}

#define CP16(sm, gm)  asm volatile("cp.async.cg.shared.global [%0], [%1], 16;" :: "r"(sm), "l"(gm) : "memory")
#define CP_COMMIT()   asm volatile("cp.async.commit_group;" ::: "memory")
#define CP_WAIT1()    asm volatile("cp.async.wait_group 1;" ::: "memory")
#define CP_WAIT0()    asm volatile("cp.async.wait_group 0;" ::: "memory")

#define LDSM_X4(r0, r1, r2, r3, addr)                                         \
    asm volatile("ldmatrix.sync.aligned.m8n8.x4.shared.b16 {%0,%1,%2,%3}, [%4];" \
        : "=r"(r0), "=r"(r1), "=r"(r2), "=r"(r3) : "r"(addr))

#define MMAFP8(c, a, b0, b1)                                                  \
    asm volatile("mma.sync.aligned.m16n8k32.row.col.f32.e4m3.e4m3.f32 "       \
        "{%0,%1,%2,%3}, {%4,%5,%6,%7}, {%8,%9}, {%0,%1,%2,%3};"               \
        : "+f"((c)[0]), "+f"((c)[1]), "+f"((c)[2]), "+f"((c)[3])              \
        : "r"((a)[0]), "r"((a)[1]), "r"((a)[2]), "r"((a)[3]), "r"(b0), "r"(b1))

#define TILE_B     16384
#define STAGE_B    32768
#define SMEM_TOTAL (1024 + 3 * STAGE_B)

// ---------------------------------------------------------------------------
// Fused kernel: norm phase (CTAs 0..255, 16 rows each) -> readiness spin ->
// persistent 2-tiles/CTA upper-triangle FP8 MMA + fused epilogue.
// All 264 CTAs are one co-resident wave (2 CTAs/SM) => spin is deadlock-free.
// ---------------------------------------------------------------------------
__global__ void __launch_bounds__(256, 2) fused_kernel(const float* __restrict__ x) {
    extern __shared__ char smem_raw[];
    uint32_t tiles = (smem_u32(smem_raw) + 1023) & ~1023u;
    float* cs_smem = reinterpret_cast<float*>(smem_raw) +
                     ((tiles - smem_u32(smem_raw)) >> 2);

    const int cta = blockIdx.x;
    const int tid = threadIdx.x, wid = tid >> 5, lane = tid & 31;
    const int wr = wid & 3, wc = wid >> 2;

    // ---- Phase 1: norm (CTAs 0..255; 2 rows/warp, sequential to cap regs) --
    if (cta < 256) {
        #pragma unroll 1
        for (int rr = 0; rr < 2; rr++) {
            int row = cta * 16 + wid * 2 + rr;
            const float4* xr = reinterpret_cast<const float4*>(x + (size_t)row * D);
            float4 v[4];
            float ss = 0.0f;
            #pragma unroll
            for (int i = 0; i < 4; i++) {
                v[i] = xr[lane + 32 * i];
                ss += v[i].x * v[i].x + v[i].y * v[i].y + v[i].z * v[i].z + v[i].w * v[i].w;
            }
            #pragma unroll
            for (int o = 16; o; o >>= 1) ss += __shfl_xor_sync(0xffffffffu, ss, o);
            float inv = (ALPHA * QS) / fmaxf(sqrtf(ss), 1e-8f);
            uint32_t* orow = reinterpret_cast<uint32_t*>(g_xq + (size_t)row * D);
            #pragma unroll
            for (int i = 0; i < 4; i++) {
                uint32_t lo = __nv_cvt_float2_to_fp8x2(make_float2(v[i].x * inv, v[i].y * inv),
                                                       __NV_SATFINITE, __NV_E4M3);
                uint32_t hi = __nv_cvt_float2_to_fp8x2(make_float2(v[i].z * inv, v[i].w * inv),
                                                       __NV_SATFINITE, __NV_E4M3);
                orow[lane + 32 * i] = lo | (hi << 16);
            }
        }
        __syncthreads();
        if (tid == 0) { __threadfence(); atomicAdd(&g_rdy[cta >> 3], 1); }
    }

    // ---- Phase 2: GEMM, 2 triangle tiles per CTA ---------------------------
    const int lr8   = lane & 7;
    const int rin16 = lr8 + ((lane >> 3) & 1) * 8;
    const int hioff = ((lane >> 4) & 1) * 16;
    const uint32_t rx = (uint32_t)lr8 << 4;
    const uint32_t offA0 = (uint32_t)(wr * 32 + rin16) * 128;
    const uint32_t offB0 = (uint32_t)(wc * 64 + rin16) * 128;

    const int rb = tid >> 3;
    const int klo = (tid & 7) * 16;
    uint32_t swo[4];
    #pragma unroll
    for (int p = 0; p < 4; p++) {
        int row = rb + 32 * p;
        swo[p] = (uint32_t)row * 128 + ((uint32_t)klo ^ ((uint32_t)(row & 7) << 4));
    }

    #pragma unroll 1
    for (int half = 0; half < 2; half++) {
        int b = cta * 2 + half, ti = 0;
        while (b >= NTILE - ti) { b -= NTILE - ti; ti++; }
        const int tj = ti + b;
        const int i0 = ti * 128, j0 = tj * 128;
        const bool diag = (ti == tj);
        const uint32_t sBoff = diag ? 0u : (uint32_t)TILE_B;

        // wait until both 128-row blocks are normalized
        if (tid == 0) {
            volatile int* rdy = g_rdy;
            while (rdy[ti] < 8 || rdy[tj] < 8) __nanosleep(32);
        }
        __syncthreads();

        const uint8_t *pA[4], *pB[4];
        #pragma unroll
        for (int p = 0; p < 4; p++) {
            int row = rb + 32 * p;
            pA[p] = g_xq + (size_t)(i0 + row) * D + klo;
            pB[p] = g_xq + (size_t)(j0 + row) * D + klo;
        }
        auto load_chunk = [&](int c, int s) {
            uint32_t bA = tiles + (uint32_t)s * STAGE_B;
            #pragma unroll
            for (int p = 0; p < 4; p++) CP16(bA + swo[p], pA[p] + c * 128);
            if (!diag) {
                uint32_t bB = bA + TILE_B;
                #pragma unroll
                for (int p = 0; p < 4; p++) CP16(bB + swo[p], pB[p] + c * 128);
            }
            CP_COMMIT();
        };

        float acc[2][8][4];
        #pragma unroll
        for (int mf = 0; mf < 2; mf++)
            #pragma unroll
            for (int nf = 0; nf < 8; nf++)
                #pragma unroll
                for (int e = 0; e < 4; e++) acc[mf][nf][e] = 0.0f;

        load_chunk(0, 0);
        load_chunk(1, 1);

        for (int c = 0; c < 4; c++) {
            if (c < 3) CP_WAIT1(); else CP_WAIT0();
            __syncthreads();
            if (c + 2 < 4) load_chunk(c + 2, (c + 2) % 3);

            uint32_t sA = tiles + (uint32_t)(c % 3) * STAGE_B;
            uint32_t sB = sA + sBoff;
            #pragma unroll
            for (int ks = 0; ks < 4; ks++) {
                uint32_t kx = ((uint32_t)(ks * 32) + hioff) ^ rx;
                uint32_t a[2][4], bb[4][4];
                #pragma unroll
                for (int mf = 0; mf < 2; mf++)
                    LDSM_X4(a[mf][0], a[mf][1], a[mf][2], a[mf][3],
                            sA + offA0 + (uint32_t)mf * 2048 + kx);
                #pragma unroll
                for (int p = 0; p < 4; p++)
                    LDSM_X4(bb[p][0], bb[p][1], bb[p][2], bb[p][3],
                            sB + offB0 + (uint32_t)p * 2048 + kx);
                #pragma unroll
                for (int mf = 0; mf < 2; mf++)
                    #pragma unroll
                    for (int nf = 0; nf < 8; nf++) {
                        int p = nf >> 1, h = nf & 1;
                        MMAFP8(acc[mf][nf], a[mf], bb[p][h], bb[p][h + 2]);
                    }
            }
        }
        __syncthreads();

        if (tj - ti == 16) {
            #pragma unroll
            for (int mf = 0; mf < 2; mf++)
                #pragma unroll
                for (int h = 0; h < 2; h++) {
                    int gi = i0 + wr * 32 + mf * 16 + (lane >> 2) + h * 8;
                    int pj = gi + HALF_N;
                    #pragma unroll
                    for (int nf = 0; nf < 8; nf++) {
                        int cb = j0 + wc * 64 + nf * 8 + (lane & 3) * 2;
                        if (cb == pj) {
                            float v = acc[mf][nf][2 * h] * LN2S;
                            g_pos[gi] = v; g_pos[pj & (N2 - 1)] = v;
                        }
                        if (cb + 1 == pj) {
                            float v = acc[mf][nf][2 * h + 1] * LN2S;
                            g_pos[gi] = v; g_pos[pj & (N2 - 1)] = v;
                        }
                    }
                }
        }

        #pragma unroll
        for (int mf = 0; mf < 2; mf++)
            #pragma unroll
            for (int nf = 0; nf < 8; nf++)
                #pragma unroll
                for (int e = 0; e < 4; e++) acc[mf][nf][e] = ex2f(acc[mf][nf][e] * SCI);

        #pragma unroll
        for (int mf = 0; mf < 2; mf++)
            #pragma unroll
            for (int h = 0; h < 2; h++) {
                float rs = 0.0f;
                #pragma unroll
                for (int nf = 0; nf < 8; nf++)
                    rs += acc[mf][nf][2 * h] + acc[mf][nf][2 * h + 1];
                rs += __shfl_xor_sync(0xffffffffu, rs, 1);
                rs += __shfl_xor_sync(0xffffffffu, rs, 2);
                if ((lane & 3) == 0) {
                    int gi = i0 + wr * 32 + mf * 16 + (lane >> 2) + h * 8;
                    g_part[(size_t)gi * NPART + tj * 2 + wc] = rs;
                }
            }

        if (!diag) {
            float cs[8][2];
            #pragma unroll
            for (int nf = 0; nf < 8; nf++) {
                cs[nf][0] = acc[0][nf][0] + acc[0][nf][2] + acc[1][nf][0] + acc[1][nf][2];
                cs[nf][1] = acc[0][nf][1] + acc[0][nf][3] + acc[1][nf][1] + acc[1][nf][3];
                #pragma unroll
                for (int o = 4; o <= 16; o <<= 1) {
                    cs[nf][0] += __shfl_xor_sync(0xffffffffu, cs[nf][0], o);
                    cs[nf][1] += __shfl_xor_sync(0xffffffffu, cs[nf][1], o);
                }
            }
            if (lane < 4) {
                #pragma unroll
                for (int nf = 0; nf < 8; nf++) {
                    cs_smem[wr * 128 + wc * 64 + nf * 8 + lane * 2]     = cs[nf][0];
                    cs_smem[wr * 128 + wc * 64 + nf * 8 + lane * 2 + 1] = cs[nf][1];
                }
            }
            __syncthreads();
            if (tid < 128) {
                float t = cs_smem[tid] + cs_smem[128 + tid] +
                          cs_smem[256 + tid] + cs_smem[384 + tid];
                g_part[(size_t)(j0 + tid) * NPART + 64 + ti] = t;
            }
        }
        __syncthreads();
    }
}

// ---------------------------------------------------------------------------
// Finalize: coalesced warp-per-row (lane l reads slots l, l+32, l+64),
// 32 blocks x 8 warps x 16 rows; last block writes mean.
// Also resets g_rdy (runs strictly after fused_kernel) for graph replays.
// ---------------------------------------------------------------------------
__global__ void __launch_bounds__(256) finalize_kernel(float* __restrict__ out) {
    const float E2 = 7.38905609893065f;   // exp(sim_ii) = e^2
    int t = threadIdx.x, wid = t >> 5, lane = t & 31;
    if (blockIdx.x == 0 && t < NTILE) g_rdy[t] = 0;
    int base = blockIdx.x * 128 + wid * 16;
    double local = 0.0;
    #pragma unroll
    for (int i = 0; i < 16; i++) {
        int r = base + i;
        const float* pr = g_part + (size_t)r * NPART;
        float s = pr[lane] + pr[lane + 32] + pr[lane + 64];
        #pragma unroll
        for (int o = 16; o; o >>= 1) s += __shfl_xor_sync(0xffffffffu, s, o);
        if (lane == 0) local += (double)(logf(s - E2) - g_pos[r]);
    }
    __shared__ double ws[8];
    __shared__ int last;
    if (lane == 0) ws[wid] = local;
    __syncthreads();
    if (t == 0) {
        double u = ws[0] + ws[1] + ws[2] + ws[3] + ws[4] + ws[5] + ws[6] + ws[7];
        g_blk[blockIdx.x] = u;
        __threadfence();
        last = (atomicAdd(&g_cnt, 1) == 31);
    }
    __syncthreads();
    if (last && t < 32) {
        double u = g_blk[t];
        #pragma unroll
        for (int o = 16; o; o >>= 1) u += __shfl_xor_sync(0xffffffffu, u, o);
        if (t == 0) { out[0] = (float)(u / (double)N2); g_cnt = 0; }
    }
}

// ---------------------------------------------------------------------------
extern "C" void kernel_launch(void* const* d_in, const int* in_sizes, int n_in,
                              void* d_out, int out_size) {
    const float* x = (const float*)d_in[0];
    float* out = (float*)d_out;

    cudaFuncSetAttribute(fused_kernel,
                         cudaFuncAttributeMaxDynamicSharedMemorySize, SMEM_TOTAL);

    fused_kernel<<<NCTA, 256, SMEM_TOTAL>>>(x);
    finalize_kernel<<<32, 256>>>(out);
}

// round 14
// speedup vs baseline: 1.1540x; 1.1540x over previous
#include <cuda_runtime.h>
#include <cuda_bf16.h>
#include <cuda_fp8.h>
#include <cstdint>
#include <math.h>

#define N2     4096
#define D      512
#define HALF_N 2048
#define NTILE  32            // 4096/128 tiles per dim
#define NBLK   528           // upper-triangular tiles: 32*33/2
#define NPART  96            // slots/row: 64 direct (tj*2+wc) + 32 transposed (ti)
#define ALPHA  1.69864360f   // sqrt(2*log2 e)
#define QS     32.0f
#define SCI    (1.0f / 1024.0f)
#define LN2S   (0.69314718056f / 1024.0f)
#define NFIN   512           // finalize blocks (8 rows each)

__device__ uint8_t g_xq[N2 * D];         // normalized, alpha*32-scaled e4m3 (2 MB)
__device__ float g_part[N2 * NPART];     // zero-init; unwritten slots stay 0
__device__ float g_pos[N2];              // positive logit per row
__device__ double g_blk[NFIN];           // per-block loss partials
__device__ int g_cnt;                    // finalize counter (self-resetting)

__device__ __forceinline__ uint32_t smem_u32(const void* p) {
    uint32_t a;
    asm("{ .reg .u64 t; cvta.to.shared.u64 t, %1; cvt.u32.u64 %0, t; }" : "=r"(a) : "l"(p));
    return a;
}
__device__ __forceinline__ float ex2f(float x) {
    float y; asm("ex2.approx.f32 %0, %1;" : "=f"(y) : "f"(x)); return y;
}

#define CP16(sm, gm)  asm volatile("cp.async.cg.shared.global [%0], [%1], 16;" :: "r"(sm), "l"(gm) : "memory")
#define CP_COMMIT()   asm volatile("cp.async.commit_group;" ::: "memory")
#define CP_WAIT1()    asm volatile("cp.async.wait_group 1;" ::: "memory")
#define CP_WAIT0()    asm volatile("cp.async.wait_group 0;" ::: "memory")

#define LDSM_X4(r0, r1, r2, r3, addr)                                         \
    asm volatile("ldmatrix.sync.aligned.m8n8.x4.shared.b16 {%0,%1,%2,%3}, [%4];" \
        : "=r"(r0), "=r"(r1), "=r"(r2), "=r"(r3) : "r"(addr))

#define MMAFP8(c, a, b0, b1)                                                  \
    asm volatile("mma.sync.aligned.m16n8k32.row.col.f32.e4m3.e4m3.f32 "       \
        "{%0,%1,%2,%3}, {%4,%5,%6,%7}, {%8,%9}, {%0,%1,%2,%3};"               \
        : "+f"((c)[0]), "+f"((c)[1]), "+f"((c)[2]), "+f"((c)[3])              \
        : "r"((a)[0]), "r"((a)[1]), "r"((a)[2]), "r"((a)[3]), "r"(b0), "r"(b1))

// ---------------------------------------------------------------------------
// Kernel 1: warp-per-row L2 norm (clamp 1e-8), e4m3 of xn*ALPHA*32
// ---------------------------------------------------------------------------
__global__ void __launch_bounds__(256) norm_kernel(const float* __restrict__ x) {
    int warp = threadIdx.x >> 5, lane = threadIdx.x & 31;
    int row = blockIdx.x * 8 + warp;
    const float4* xr = reinterpret_cast<const float4*>(x + (size_t)row * D);
    float4 v[4];
    float ss = 0.0f;
    #pragma unroll
    for (int i = 0; i < 4; i++) {
        v[i] = xr[lane + 32 * i];
        ss += v[i].x * v[i].x + v[i].y * v[i].y + v[i].z * v[i].z + v[i].w * v[i].w;
    }
    #pragma unroll
    for (int o = 16; o; o >>= 1) ss += __shfl_xor_sync(0xffffffffu, ss, o);
    float inv = (ALPHA * QS) / fmaxf(sqrtf(ss), 1e-8f);
    uint32_t* orow = reinterpret_cast<uint32_t*>(g_xq + (size_t)row * D);
    #pragma unroll
    for (int i = 0; i < 4; i++) {
        uint32_t lo = __nv_cvt_float2_to_fp8x2(make_float2(v[i].x * inv, v[i].y * inv),
                                               __NV_SATFINITE, __NV_E4M3);
        uint32_t hi = __nv_cvt_float2_to_fp8x2(make_float2(v[i].z * inv, v[i].w * inv),
                                               __NV_SATFINITE, __NV_E4M3);
        orow[lane + 32 * i] = lo | (hi << 16);
    }
}

// ---------------------------------------------------------------------------
// Kernel 2: persistent 2-tiles/CTA upper-triangle FP8 MMA + fused epilogue
// (unchanged: the proven ~26us configuration)
// ---------------------------------------------------------------------------
#define TILE_B     16384
#define STAGE_B    32768
#define SMEM_TOTAL (1024 + 3 * STAGE_B)

__global__ void __launch_bounds__(256, 2) simexp_mma_kernel() {
    extern __shared__ char smem_raw[];
    uint32_t tiles = (smem_u32(smem_raw) + 1023) & ~1023u;
    float* cs_smem = reinterpret_cast<float*>(smem_raw) +
                     ((tiles - smem_u32(smem_raw)) >> 2);

    const int tid = threadIdx.x, wid = tid >> 5, lane = tid & 31;
    const int wr = wid & 3, wc = wid >> 2;

    const int lr8   = lane & 7;
    const int rin16 = lr8 + ((lane >> 3) & 1) * 8;
    const int hioff = ((lane >> 4) & 1) * 16;
    const uint32_t rx = (uint32_t)lr8 << 4;
    const uint32_t offA0 = (uint32_t)(wr * 32 + rin16) * 128;
    const uint32_t offB0 = (uint32_t)(wc * 64 + rin16) * 128;

    const int rb = tid >> 3;
    const int klo = (tid & 7) * 16;
    uint32_t swo[4];
    #pragma unroll
    for (int p = 0; p < 4; p++) {
        int row = rb + 32 * p;
        swo[p] = (uint32_t)row * 128 + ((uint32_t)klo ^ ((uint32_t)(row & 7) << 4));
    }

    #pragma unroll 1
    for (int half = 0; half < 2; half++) {
        int b = blockIdx.x * 2 + half, ti = 0;
        while (b >= NTILE - ti) { b -= NTILE - ti; ti++; }
        const int tj = ti + b;
        const int i0 = ti * 128, j0 = tj * 128;
        const bool diag = (ti == tj);
        const uint32_t sBoff = diag ? 0u : (uint32_t)TILE_B;

        const uint8_t *pA[4], *pB[4];
        #pragma unroll
        for (int p = 0; p < 4; p++) {
            int row = rb + 32 * p;
            pA[p] = g_xq + (size_t)(i0 + row) * D + klo;
            pB[p] = g_xq + (size_t)(j0 + row) * D + klo;
        }
        auto load_chunk = [&](int c, int s) {
            uint32_t bA = tiles + (uint32_t)s * STAGE_B;
            #pragma unroll
            for (int p = 0; p < 4; p++) CP16(bA + swo[p], pA[p] + c * 128);
            if (!diag) {
                uint32_t bB = bA + TILE_B;
                #pragma unroll
                for (int p = 0; p < 4; p++) CP16(bB + swo[p], pB[p] + c * 128);
            }
            CP_COMMIT();
        };

        float acc[2][8][4];
        #pragma unroll
        for (int mf = 0; mf < 2; mf++)
            #pragma unroll
            for (int nf = 0; nf < 8; nf++)
                #pragma unroll
                for (int e = 0; e < 4; e++) acc[mf][nf][e] = 0.0f;

        load_chunk(0, 0);
        load_chunk(1, 1);

        for (int c = 0; c < 4; c++) {
            if (c < 3) CP_WAIT1(); else CP_WAIT0();
            __syncthreads();
            if (c + 2 < 4) load_chunk(c + 2, (c + 2) % 3);

            uint32_t sA = tiles + (uint32_t)(c % 3) * STAGE_B;
            uint32_t sB = sA + sBoff;
            #pragma unroll
            for (int ks = 0; ks < 4; ks++) {
                uint32_t kx = ((uint32_t)(ks * 32) + hioff) ^ rx;
                uint32_t a[2][4], bb[4][4];
                #pragma unroll
                for (int mf = 0; mf < 2; mf++)
                    LDSM_X4(a[mf][0], a[mf][1], a[mf][2], a[mf][3],
                            sA + offA0 + (uint32_t)mf * 2048 + kx);
                #pragma unroll
                for (int p = 0; p < 4; p++)
                    LDSM_X4(bb[p][0], bb[p][1], bb[p][2], bb[p][3],
                            sB + offB0 + (uint32_t)p * 2048 + kx);
                #pragma unroll
                for (int mf = 0; mf < 2; mf++)
                    #pragma unroll
                    for (int nf = 0; nf < 8; nf++) {
                        int p = nf >> 1, h = nf & 1;
                        MMAFP8(acc[mf][nf], a[mf], bb[p][h], bb[p][h + 2]);
                    }
            }
        }
        __syncthreads();

        if (tj - ti == 16) {
            #pragma unroll
            for (int mf = 0; mf < 2; mf++)
                #pragma unroll
                for (int h = 0; h < 2; h++) {
                    int gi = i0 + wr * 32 + mf * 16 + (lane >> 2) + h * 8;
                    int pj = gi + HALF_N;
                    #pragma unroll
                    for (int nf = 0; nf < 8; nf++) {
                        int cb = j0 + wc * 64 + nf * 8 + (lane & 3) * 2;
                        if (cb == pj) {
                            float v = acc[mf][nf][2 * h] * LN2S;
                            g_pos[gi] = v; g_pos[pj & (N2 - 1)] = v;
                        }
                        if (cb + 1 == pj) {
                            float v = acc[mf][nf][2 * h + 1] * LN2S;
                            g_pos[gi] = v; g_pos[pj & (N2 - 1)] = v;
                        }
                    }
                }
        }

        #pragma unroll
        for (int mf = 0; mf < 2; mf++)
            #pragma unroll
            for (int nf = 0; nf < 8; nf++)
                #pragma unroll
                for (int e = 0; e < 4; e++) acc[mf][nf][e] = ex2f(acc[mf][nf][e] * SCI);

        #pragma unroll
        for (int mf = 0; mf < 2; mf++)
            #pragma unroll
            for (int h = 0; h < 2; h++) {
                float rs = 0.0f;
                #pragma unroll
                for (int nf = 0; nf < 8; nf++)
                    rs += acc[mf][nf][2 * h] + acc[mf][nf][2 * h + 1];
                rs += __shfl_xor_sync(0xffffffffu, rs, 1);
                rs += __shfl_xor_sync(0xffffffffu, rs, 2);
                if ((lane & 3) == 0) {
                    int gi = i0 + wr * 32 + mf * 16 + (lane >> 2) + h * 8;
                    g_part[(size_t)gi * NPART + tj * 2 + wc] = rs;
                }
            }

        if (!diag) {
            float cs[8][2];
            #pragma unroll
            for (int nf = 0; nf < 8; nf++) {
                cs[nf][0] = acc[0][nf][0] + acc[0][nf][2] + acc[1][nf][0] + acc[1][nf][2];
                cs[nf][1] = acc[0][nf][1] + acc[0][nf][3] + acc[1][nf][1] + acc[1][nf][3];
                #pragma unroll
                for (int o = 4; o <= 16; o <<= 1) {
                    cs[nf][0] += __shfl_xor_sync(0xffffffffu, cs[nf][0], o);
                    cs[nf][1] += __shfl_xor_sync(0xffffffffu, cs[nf][1], o);
                }
            }
            if (lane < 4) {
                #pragma unroll
                for (int nf = 0; nf < 8; nf++) {
                    cs_smem[wr * 128 + wc * 64 + nf * 8 + lane * 2]     = cs[nf][0];
                    cs_smem[wr * 128 + wc * 64 + nf * 8 + lane * 2 + 1] = cs[nf][1];
                }
            }
            __syncthreads();
            if (tid < 128) {
                float t = cs_smem[tid] + cs_smem[128 + tid] +
                          cs_smem[256 + tid] + cs_smem[384 + tid];
                g_part[(size_t)(j0 + tid) * NPART + 64 + ti] = t;
            }
        }
        __syncthreads();
    }
}

// ---------------------------------------------------------------------------
// Kernel 3: warp-per-row finalize. 512 blocks x 8 warps = 4096 warps, one row
// each: 3 coalesced loads (single round-trip, MLP), reduce, logf. No serial
// iteration chain. Last-arrival block reduces the 512 double partials.
// ---------------------------------------------------------------------------
__global__ void __launch_bounds__(256) finalize_kernel(float* __restrict__ out) {
    const float E2 = 7.38905609893065f;   // exp(sim_ii) = e^2
    int t = threadIdx.x, wid = t >> 5, lane = t & 31;
    int r = blockIdx.x * 8 + wid;
    const float* pr = g_part + (size_t)r * NPART;
    float s = pr[lane] + pr[lane + 32] + pr[lane + 64];
    #pragma unroll
    for (int o = 16; o; o >>= 1) s += __shfl_xor_sync(0xffffffffu, s, o);
    __shared__ double ws[8];
    __shared__ int last;
    if (lane == 0) ws[wid] = (double)(logf(s - E2) - g_pos[r]);
    __syncthreads();
    if (t == 0) {
        double u = ws[0] + ws[1] + ws[2] + ws[3] + ws[4] + ws[5] + ws[6] + ws[7];
        g_blk[blockIdx.x] = u;
        __threadfence();
        last = (atomicAdd(&g_cnt, 1) == NFIN - 1);
    }
    __syncthreads();
    if (last) {
        // deterministic tree over the 512 partials (independent of arrival order)
        double u = g_blk[t] + g_blk[t + 256];
        #pragma unroll
        for (int o = 16; o; o >>= 1) u += __shfl_xor_sync(0xffffffffu, u, o);
        if (lane == 0) ws[wid] = u;
        __syncthreads();
        if (t == 0) {
            double v = ws[0] + ws[1] + ws[2] + ws[3] + ws[4] + ws[5] + ws[6] + ws[7];
            out[0] = (float)(v / (double)N2);
            g_cnt = 0;
        }
    }
}

// ---------------------------------------------------------------------------
extern "C" void kernel_launch(void* const* d_in, const int* in_sizes, int n_in,
                              void* d_out, int out_size) {
    const float* x = (const float*)d_in[0];
    float* out = (float*)d_out;

    cudaFuncSetAttribute(simexp_mma_kernel,
                         cudaFuncAttributeMaxDynamicSharedMemorySize, SMEM_TOTAL);

    norm_kernel<<<N2 / 8, 256>>>(x);
    simexp_mma_kernel<<<NBLK / 2, 256, SMEM_TOTAL>>>();
    finalize_kernel<<<NFIN, 256>>>(out);
}